// round 10
// baseline (speedup 1.0000x reference)
#include <cuda_runtime.h>

// Problem constants (fixed by the dataset reference)
#define BB   8
#define NN   2048
#define CC   16
#define HID  128
#define RFN  16384      // 128*128 receptive fields
#define KTOT 144        // C + HID
#define GATES 512       // 4*HID
#define K4   (KTOT/4)   // 36 float4 groups along K
#define OUT_ELEMS (BB*HID*128*128)

#define PLAN_BLOCKS 8
#define PREP_GRID   520
#define LSTM_GRID   296   // one full wave at 2 blocks/SM
#define MUL_SLOTS   256   // blocks 0..255 may own a multi group
#define CM          4     // multi chains per block-group

// ---------------- device scratch (no allocations allowed) ----------------
__device__ int    g_sorted[BB*NN];     // per batch: event ids sorted by (rf, time)
__device__ int    g_single[BB*NN];     // per batch: ev | rf<<11
__device__ int2   g_mult[BB*NN];       // per batch: {rf | off<<14, len}
__device__ int    g_ns[BB], g_nm[BB];
__device__ float  g_WT[CC*GATES];      // x-part weights, [k][gate] (singles)
__device__ float4 g_W4[K4*4*HID];      // [(k4*4+q)*128 + h] = W[q*128+h][4k4..4k4+3]
__device__ float  g_bias[GATES];

// ---------------- helpers ----------------
__device__ __forceinline__ float sigmoidf_(float x) {
    return __fdividef(1.0f, 1.0f + __expf(-x));
}
__device__ __forceinline__ float tanhf_(float x) {
    float ax = fabsf(x);
    float e  = __expf(-2.0f * ax);
    float t  = __fdividef(1.0f - e, 1.0f + e);
    return copysignf(t, x);
}
__device__ __forceinline__ unsigned long long dup2_(float v) {
    unsigned long long r;
    asm("mov.b64 %0, {%1, %1};" : "=l"(r) : "f"(v));
    return r;
}
__device__ __forceinline__ void fma2_(unsigned long long& d, unsigned long long a,
                                      unsigned long long b) {
    asm("fma.rn.f32x2 %0, %1, %2, %3;" : "=l"(d) : "l"(a), "l"(b), "l"(d));
}
__device__ __forceinline__ unsigned long long add2_(unsigned long long a,
                                                    unsigned long long b) {
    unsigned long long r;
    asm("add.rn.f32x2 %0, %1, %2;" : "=l"(r) : "l"(a), "l"(b));
    return r;
}
__device__ __forceinline__ float2 unpack2_(unsigned long long v) {
    float2 r;
    asm("mov.b64 {%0, %1}, %2;" : "=f"(r.x), "=f"(r.y) : "l"(v));
    return r;
}

// K0: fused prep. Blocks 0..7: per-batch plan (counting sort + chain lists).
// Blocks 8..: zero 64MB output + build weight layouts (runs concurrently).
__global__ void __launch_bounds__(1024) k_prep(float4* __restrict__ out,
                       const int* __restrict__ coords,
                       const float* __restrict__ w_ih, const float* __restrict__ w_hh,
                       const float* __restrict__ b_ih, const float* __restrict__ b_hh) {
    __shared__ unsigned int pcnt[RFN/2];     // two u16 counters per int (32KB)
    __shared__ unsigned short srf[NN];
    __shared__ unsigned short sev[NN];
    __shared__ int sscan[1024];
    int tid = threadIdx.x;

    if (blockIdx.x >= PLAN_BLOCKS) {
        // ---- fill + weight path ----
        int i = (blockIdx.x - PLAN_BLOCKS)*1024 + tid;
        int stride = (PREP_GRID - PLAN_BLOCKS)*1024;
        const float4 z = make_float4(0.f, 0.f, 0.f, 0.f);
        for (int t = i; t < OUT_ELEMS/4; t += stride) out[t] = z;
        for (int t = i; t < CC*GATES; t += stride) {
            int k = t / GATES, g = t % GATES;
            g_WT[t] = w_ih[g*CC + k];
        }
        for (int t = i; t < K4*4*HID; t += stride) {
            int k4 = t / (4*HID);
            int rem = t % (4*HID);
            int q = rem / HID, h = rem % HID;
            int g = q*HID + h;
            float v[4];
            #pragma unroll
            for (int j = 0; j < 4; j++) {
                int k = k4*4 + j;
                v[j] = (k < CC) ? w_ih[g*CC + k] : w_hh[g*HID + (k - CC)];
            }
            g_W4[t] = make_float4(v[0], v[1], v[2], v[3]);
        }
        for (int t = i; t < GATES; t += stride) g_bias[t] = b_ih[t] + b_hh[t];
        return;
    }

    // ---- plan path (one block per batch) ----
    int b = blockIdx.x;
    if (tid == 0) { g_ns[b] = 0; g_nm[b] = 0; }
    #pragma unroll
    for (int j = 0; j < 8; j++) pcnt[tid + j*1024] = 0;
    __syncthreads();

    int n0 = tid, n1 = tid + 1024;
    int x0 = coords[(b*NN + n0)*2], y0 = coords[(b*NN + n0)*2 + 1];
    int x1 = coords[(b*NN + n1)*2], y1 = coords[(b*NN + n1)*2 + 1];
    int rf0 = y0*128 + x0, rf1 = y1*128 + x1;
    atomicAdd(&pcnt[rf0 >> 1], 1u << ((rf0 & 1)*16));
    atomicAdd(&pcnt[rf1 >> 1], 1u << ((rf1 & 1)*16));
    __syncthreads();

    unsigned int ex[8];
    int run = 0;
    #pragma unroll
    for (int j = 0; j < 8; j++) {
        unsigned int v = pcnt[tid*8 + j];
        int c0 = v & 0xFFFF, c1 = v >> 16;
        int e0 = run; run += c0;
        int e1 = run; run += c1;
        ex[j] = (unsigned)e0 | ((unsigned)e1 << 16);
    }
    sscan[tid] = run;
    __syncthreads();
    for (int d = 1; d < 1024; d <<= 1) {
        int v = (tid >= d) ? sscan[tid - d] : 0;
        __syncthreads();
        sscan[tid] += v;
        __syncthreads();
    }
    unsigned int prev = (unsigned)(sscan[tid] - run);
    unsigned int prevp = prev * 0x00010001u;
    #pragma unroll
    for (int j = 0; j < 8; j++) pcnt[tid*8 + j] = ex[j] + prevp;
    __syncthreads();

    {
        unsigned int p = atomicAdd(&pcnt[rf0 >> 1], 1u << ((rf0 & 1)*16));
        int pos = (p >> ((rf0 & 1)*16)) & 0xFFFF;
        sev[pos] = (unsigned short)n0; srf[pos] = (unsigned short)rf0;
        p = atomicAdd(&pcnt[rf1 >> 1], 1u << ((rf1 & 1)*16));
        pos = (p >> ((rf1 & 1)*16)) & 0xFFFF;
        sev[pos] = (unsigned short)n1; srf[pos] = (unsigned short)rf1;
    }
    __syncthreads();

    // pass A: restore time order inside each bucket (tiny insertion sorts)
    #pragma unroll
    for (int s = 0; s < 2; s++) {
        int i = tid + s*1024;
        int rf = srf[i];
        int pv = (i == 0) ? -1 : (int)srf[i-1];
        if (rf != pv) {
            int L = 1;
            while (i + L < NN && srf[i+L] == rf) L++;
            if (L > 1) {
                for (int a = 1; a < L; a++) {
                    unsigned short v = sev[i+a];
                    int j = a - 1;
                    while (j >= 0 && sev[i+j] > v) { sev[i+j+1] = sev[i+j]; j--; }
                    sev[i+j+1] = v;
                }
            }
        }
    }
    __syncthreads();

    // pass B: emit chain records + dump sorted event ids
    #pragma unroll
    for (int s = 0; s < 2; s++) {
        int i = tid + s*1024;
        g_sorted[b*NN + i] = sev[i];
        int rf = srf[i];
        int pv = (i == 0) ? -1 : (int)srf[i-1];
        bool isb = (rf != pv);
        int L = 0;
        if (isb) {
            L = 1;
            while (i + L < NN && srf[i+L] == rf) L++;
        }
        bool sgl = isb && (L == 1);
        unsigned bal = __ballot_sync(0xffffffffu, sgl);
        if (sgl) {
            int lane = tid & 31;
            int leader = __ffs(bal) - 1;
            int base = 0;
            if (lane == leader) base = atomicAdd(&g_ns[b], __popc(bal));
            base = __shfl_sync(bal, base, leader);
            g_single[b*NN + base + __popc(bal & ((1u << lane) - 1))] =
                (int)sev[i] | (rf << 11);
        } else if (isb) {
            int idx = atomicAdd(&g_nm[b], 1);
            g_mult[b*NN + idx] = make_int2(rf | (i << 14), L);
        }
    }
}

// K1: unified LSTM. Every block: (maybe) one multi chain-group (CM=4, f32x2,
// split-K s∈{0,1}), then grid-stride over ALL singles (f32x2, weights from L1).
__global__ void __launch_bounds__(256, 2) k_lstm(const float* __restrict__ feat,
                                                 float* __restrict__ out) {
    __shared__ __align__(16) float ivt[KTOT][CM];   // transposed [k][chain]
    __shared__ float xsh[8][4][CC];
    __shared__ int slen[CM], soff[CM];
    __shared__ int2 mds[CM];

    int tid = threadIdx.x;
    int lane = tid & 31, warp = tid >> 5;

    // ================= phase 1: multi-event chains =================
    if (blockIdx.x < MUL_SLOTS) {
        int bb  = blockIdx.x & 7;
        int sub = blockIdx.x >> 3;          // 0..31
        int h = tid >> 1;                   // hidden unit 0..127
        int s = tid & 1;                    // K slice 0..1 (18 float4-groups)
        int nm = g_nm[bb];

        unsigned long long bi2 = dup2_(g_bias[h]);
        unsigned long long bf2 = dup2_(g_bias[128 + h]);
        unsigned long long bg2 = dup2_(g_bias[256 + h]);
        unsigned long long bo2 = dup2_(g_bias[384 + h]);

        for (int grp = sub*CM; grp < nm; grp += 32*CM) {
            if (tid < CM) {
                int ci = grp + tid;
                int2 m = (ci < nm) ? g_mult[bb*NN + ci] : make_int2(0, 0);
                mds[tid] = m;
                slen[tid] = m.y;
                soff[tid] = m.x >> 14;
            }
            __syncthreads();
            int rf[CM], len[CM];
            int maxlen = 0;
            #pragma unroll
            for (int c = 0; c < CM; c++) {
                int2 m = mds[c];
                rf[c] = m.x & 0x3FFF;
                len[c] = m.y;
                maxlen = max(maxlen, len[c]);
            }
            float cst[CM];
            #pragma unroll
            for (int c = 0; c < CM; c++) cst[c] = 0.f;

            for (int r = 0; r < maxlen; r++) {
                if (tid < CM*CC) {                 // stage x, transposed
                    int c = tid >> 4, k = tid & 15;
                    if (slen[c] > r) {
                        int e = g_sorted[bb*NN + soff[c] + r];
                        ivt[k][c] = feat[(bb*NN + e)*CC + k];
                    }
                }
                __syncthreads();

                // acc[p][q]: packed pair p = chains {2p, 2p+1}, gate q
                unsigned long long acc[2][4];
                if (s == 0) {
                    acc[0][0] = bi2; acc[0][1] = bf2; acc[0][2] = bg2; acc[0][3] = bo2;
                    acc[1][0] = bi2; acc[1][1] = bf2; acc[1][2] = bg2; acc[1][3] = bo2;
                } else {
                    #pragma unroll
                    for (int p = 0; p < 2; p++)
                        #pragma unroll
                        for (int q = 0; q < 4; q++) acc[p][q] = 0ull;
                }

                int k4lo, k4hi;
                if (r == 0) { k4lo = 0; k4hi = (s == 0) ? CC/4 : 0; }
                else        { k4lo = s*18; k4hi = s*18 + 18; }

                for (int k4 = k4lo; k4 < k4hi; k4++) {
                    int basew = (k4 << 2)*HID + h;
                    float4 w0 = g_W4[basew];
                    float4 w1 = g_W4[basew + HID];
                    float4 w2 = g_W4[basew + 2*HID];
                    float4 w3 = g_W4[basew + 3*HID];
                    const float* w0p = (const float*)&w0;
                    const float* w1p = (const float*)&w1;
                    const float* w2p = (const float*)&w2;
                    const float* w3p = (const float*)&w3;
                    #pragma unroll
                    for (int kk = 0; kk < 4; kk++) {
                        int k = k4*4 + kk;
                        unsigned long long iv0 = *(const unsigned long long*)&ivt[k][0];
                        unsigned long long iv1 = *(const unsigned long long*)&ivt[k][2];
                        unsigned long long d0 = dup2_(w0p[kk]);
                        unsigned long long d1 = dup2_(w1p[kk]);
                        unsigned long long d2 = dup2_(w2p[kk]);
                        unsigned long long d3 = dup2_(w3p[kk]);
                        fma2_(acc[0][0], iv0, d0); fma2_(acc[1][0], iv1, d0);
                        fma2_(acc[0][1], iv0, d1); fma2_(acc[1][1], iv1, d1);
                        fma2_(acc[0][2], iv0, d2); fma2_(acc[1][2], iv1, d2);
                        fma2_(acc[0][3], iv0, d3); fma2_(acc[1][3], iv1, d3);
                    }
                }
                __syncthreads();                   // all ivt reads done

                // reduce the two split-K lanes (adjacent in warp)
                #pragma unroll
                for (int p = 0; p < 2; p++)
                    #pragma unroll
                    for (int q = 0; q < 4; q++)
                        acc[p][q] = add2_(acc[p][q],
                                          __shfl_xor_sync(0xffffffffu, acc[p][q], 1));

                float hn[CM];
                #pragma unroll
                for (int p = 0; p < 2; p++) {
                    float2 gi = unpack2_(acc[p][0]);
                    float2 gf = unpack2_(acc[p][1]);
                    float2 gg = unpack2_(acc[p][2]);
                    float2 go = unpack2_(acc[p][3]);
                    #pragma unroll
                    for (int half = 0; half < 2; half++) {
                        int c = 2*p + half;
                        float vi = half ? gi.y : gi.x;
                        float vf = half ? gf.y : gf.x;
                        float vg = half ? gg.y : gg.x;
                        float vo = half ? go.y : go.x;
                        float ig = sigmoidf_(vi), fg = sigmoidf_(vf);
                        float g2 = tanhf_(vg),   og = sigmoidf_(vo);
                        cst[c] = fg*cst[c] + ig*g2;
                        hn[c] = og * tanhf_(cst[c]);
                    }
                }
                if (s == 0) {
                    // write h back transposed (one STS.128) + final outputs
                    *(float4*)&ivt[CC + h][0] = make_float4(hn[0], hn[1], hn[2], hn[3]);
                    #pragma unroll
                    for (int c = 0; c < CM; c++) {
                        if (len[c] == r + 1) {
                            int y = rf[c] >> 7, x = rf[c] & 127;
                            out[((bb*HID + h)*128 + y)*128 + x] = hn[c];
                        }
                    }
                }
                __syncthreads();                   // h writes before next read
            }
            __syncthreads();
        }
    }

    // ================= phase 2: singleton chains (all blocks) =================
    for (int bb = 0; bb < BB; bb++) {
        int ns = g_ns[bb];
        for (int base0 = blockIdx.x * 32; base0 < ns; base0 += LSTM_GRID * 32) {
            int idx0 = base0 + (warp << 2);
            if (idx0 >= ns) continue;

            int rec = -1;
            if (lane < 4 && idx0 + lane < ns) rec = g_single[bb*NN + idx0 + lane];
            __syncwarp();
            #pragma unroll
            for (int s2 = 0; s2 < 2; s2++) {
                int slot = lane + (s2 << 5);
                int c = slot >> 4, k = slot & 15;
                int rc = __shfl_sync(0xffffffffu, rec, c);
                if (rc >= 0) {
                    int ev = rc & 2047;
                    xsh[warp][c][k] = feat[(bb*NN + ev)*CC + k];
                }
            }
            __syncwarp();

            // acc pairs: acc2[c][2q+p] = gates q*128 + lane*4 + 2p + {0,1}
            unsigned long long acc2[4][8];
            #pragma unroll
            for (int q = 0; q < 4; q++) {
                ulonglong2 bq = *(const ulonglong2*)&g_bias[q*128 + (lane << 2)];
                #pragma unroll
                for (int c = 0; c < 4; c++) {
                    acc2[c][2*q]   = bq.x;
                    acc2[c][2*q+1] = bq.y;
                }
            }
            #pragma unroll 4
            for (int k = 0; k < CC; k++) {
                const ulonglong2* wp = (const ulonglong2*)&g_WT[k*GATES + (lane << 2)];
                ulonglong2 w0 = wp[0];
                ulonglong2 w1 = wp[32];
                ulonglong2 w2 = wp[64];
                ulonglong2 w3 = wp[96];
                #pragma unroll
                for (int c = 0; c < 4; c++) {
                    unsigned long long iv2 = dup2_(xsh[warp][c][k]);
                    fma2_(acc2[c][0], iv2, w0.x); fma2_(acc2[c][1], iv2, w0.y);
                    fma2_(acc2[c][2], iv2, w1.x); fma2_(acc2[c][3], iv2, w1.y);
                    fma2_(acc2[c][4], iv2, w2.x); fma2_(acc2[c][5], iv2, w2.y);
                    fma2_(acc2[c][6], iv2, w3.x); fma2_(acc2[c][7], iv2, w3.y);
                }
            }
            #pragma unroll
            for (int c = 0; c < 4; c++) {
                int rc = __shfl_sync(0xffffffffu, rec, c);
                if (rc >= 0) {
                    int rf = rc >> 11;
                    int y = rf >> 7, x = rf & 127;
                    float2 i0 = unpack2_(acc2[c][0]), i1 = unpack2_(acc2[c][1]);
                    float2 g0 = unpack2_(acc2[c][4]), g1 = unpack2_(acc2[c][5]);
                    float2 o0 = unpack2_(acc2[c][6]), o1 = unpack2_(acc2[c][7]);
                    float gi[4] = {i0.x, i0.y, i1.x, i1.y};
                    float gg[4] = {g0.x, g0.y, g1.x, g1.y};
                    float go[4] = {o0.x, o0.y, o1.x, o1.y};
                    #pragma unroll
                    for (int i = 0; i < 4; i++) {
                        float cn = sigmoidf_(gi[i]) * tanhf_(gg[i]);   // c_prev=0, f dead
                        float hh = sigmoidf_(go[i]) * tanhf_(cn);
                        out[((bb*HID + (lane << 2) + i)*128 + y)*128 + x] = hh;
                    }
                }
            }
        }
    }
}

extern "C" void kernel_launch(void* const* d_in, const int* in_sizes, int n_in,
                              void* d_out, int out_size) {
    const float* features = (const float*)d_in[0];
    const int*   coords   = (const int*)  d_in[1];
    const float* w_ih     = (const float*)d_in[2];
    const float* w_hh     = (const float*)d_in[3];
    const float* b_ih     = (const float*)d_in[4];
    const float* b_hh     = (const float*)d_in[5];
    float* out = (float*)d_out;

    k_prep<<<PREP_GRID, 1024>>>((float4*)out, coords, w_ih, w_hh, b_ih, b_hh);
    k_lstm<<<LSTM_GRID, 256>>>(features, out);
}

// round 11
// speedup vs baseline: 1.3197x; 1.3197x over previous
#include <cuda_runtime.h>

// Problem constants (fixed by the dataset reference)
#define BB   8
#define NN   2048
#define CC   16
#define HID  128
#define RFN  16384      // 128*128 receptive fields
#define KTOT 144        // C + HID
#define GATES 512       // 4*HID
#define K4   (KTOT/4)   // 36 float4 groups along K
#define OUT_ELEMS (BB*HID*128*128)

#define PLAN_BLOCKS 8
#define PREP_GRID   520
#define LSTM_GRID   296   // one full wave at 2 blocks/SM
#define MUL_SLOTS   256   // blocks 0..255 own multi groups (32 subs per batch)
#define CM          8     // multi chains per block-group
#define QUAD_SLOTS  (BB*512)            // per-batch 512 quads of 4 singles
#define QUAD_UNITS  (LSTM_GRID*8)       // warp-units striding the quad slots

// ---------------- device scratch (no allocations allowed) ----------------
__device__ int    g_sorted[BB*NN];     // per batch: event ids sorted by (rf, time)
__device__ int    g_single[BB*NN];     // per batch: ev | rf<<11
__device__ int2   g_mult[BB*NN];       // per batch: {rf | off<<14, len}
__device__ int    g_ns[BB], g_nm[BB];
__device__ float  g_WT[CC*GATES];      // x-part weights, [k][gate] (singles)
__device__ float4 g_W4[K4*4*HID];      // [(k4*4+q)*128 + h] = W[q*128+h][4k4..4k4+3]
__device__ float  g_bias[GATES];

// ---------------- helpers ----------------
__device__ __forceinline__ float sigmoidf_(float x) {
    return __fdividef(1.0f, 1.0f + __expf(-x));
}
__device__ __forceinline__ float tanhf_(float x) {
    float ax = fabsf(x);
    float e  = __expf(-2.0f * ax);
    float t  = __fdividef(1.0f - e, 1.0f + e);
    return copysignf(t, x);
}
__device__ __forceinline__ unsigned long long dup2_(float v) {
    unsigned long long r;
    asm("mov.b64 %0, {%1, %1};" : "=l"(r) : "f"(v));
    return r;
}
__device__ __forceinline__ void fma2_(unsigned long long& d, unsigned long long a,
                                      unsigned long long b) {
    asm("fma.rn.f32x2 %0, %1, %2, %3;" : "=l"(d) : "l"(a), "l"(b), "l"(d));
}
__device__ __forceinline__ float2 unpack2_(unsigned long long v) {
    float2 r;
    asm("mov.b64 {%0, %1}, %2;" : "=f"(r.x), "=f"(r.y) : "l"(v));
    return r;
}

// K0: fused prep. Blocks 0..7: per-batch plan (counting sort + chain lists).
// Blocks 8..: zero 64MB output + build weight layouts (runs concurrently).
__global__ void __launch_bounds__(1024) k_prep(float4* __restrict__ out,
                       const int* __restrict__ coords,
                       const float* __restrict__ w_ih, const float* __restrict__ w_hh,
                       const float* __restrict__ b_ih, const float* __restrict__ b_hh) {
    __shared__ unsigned int pcnt[RFN/2];     // two u16 counters per int (32KB)
    __shared__ unsigned short srf[NN];
    __shared__ unsigned short sev[NN];
    __shared__ int sscan[1024];
    int tid = threadIdx.x;

    if (blockIdx.x >= PLAN_BLOCKS) {
        // ---- fill + weight path ----
        int i = (blockIdx.x - PLAN_BLOCKS)*1024 + tid;
        int stride = (PREP_GRID - PLAN_BLOCKS)*1024;
        const float4 z = make_float4(0.f, 0.f, 0.f, 0.f);
        for (int t = i; t < OUT_ELEMS/4; t += stride) out[t] = z;
        for (int t = i; t < CC*GATES; t += stride) {
            int k = t / GATES, g = t % GATES;
            g_WT[t] = w_ih[g*CC + k];
        }
        for (int t = i; t < K4*4*HID; t += stride) {
            int k4 = t / (4*HID);
            int rem = t % (4*HID);
            int q = rem / HID, h = rem % HID;
            int g = q*HID + h;
            float v[4];
            #pragma unroll
            for (int j = 0; j < 4; j++) {
                int k = k4*4 + j;
                v[j] = (k < CC) ? w_ih[g*CC + k] : w_hh[g*HID + (k - CC)];
            }
            g_W4[t] = make_float4(v[0], v[1], v[2], v[3]);
        }
        for (int t = i; t < GATES; t += stride) g_bias[t] = b_ih[t] + b_hh[t];
        return;
    }

    // ---- plan path (one block per batch) ----
    int b = blockIdx.x;
    if (tid == 0) { g_ns[b] = 0; g_nm[b] = 0; }
    #pragma unroll
    for (int j = 0; j < 8; j++) pcnt[tid + j*1024] = 0;
    __syncthreads();

    int n0 = tid, n1 = tid + 1024;
    int x0 = coords[(b*NN + n0)*2], y0 = coords[(b*NN + n0)*2 + 1];
    int x1 = coords[(b*NN + n1)*2], y1 = coords[(b*NN + n1)*2 + 1];
    int rf0 = y0*128 + x0, rf1 = y1*128 + x1;
    atomicAdd(&pcnt[rf0 >> 1], 1u << ((rf0 & 1)*16));
    atomicAdd(&pcnt[rf1 >> 1], 1u << ((rf1 & 1)*16));
    __syncthreads();

    unsigned int ex[8];
    int run = 0;
    #pragma unroll
    for (int j = 0; j < 8; j++) {
        unsigned int v = pcnt[tid*8 + j];
        int c0 = v & 0xFFFF, c1 = v >> 16;
        int e0 = run; run += c0;
        int e1 = run; run += c1;
        ex[j] = (unsigned)e0 | ((unsigned)e1 << 16);
    }
    sscan[tid] = run;
    __syncthreads();
    for (int d = 1; d < 1024; d <<= 1) {
        int v = (tid >= d) ? sscan[tid - d] : 0;
        __syncthreads();
        sscan[tid] += v;
        __syncthreads();
    }
    unsigned int prev = (unsigned)(sscan[tid] - run);
    unsigned int prevp = prev * 0x00010001u;
    #pragma unroll
    for (int j = 0; j < 8; j++) pcnt[tid*8 + j] = ex[j] + prevp;
    __syncthreads();

    {
        unsigned int p = atomicAdd(&pcnt[rf0 >> 1], 1u << ((rf0 & 1)*16));
        int pos = (p >> ((rf0 & 1)*16)) & 0xFFFF;
        sev[pos] = (unsigned short)n0; srf[pos] = (unsigned short)rf0;
        p = atomicAdd(&pcnt[rf1 >> 1], 1u << ((rf1 & 1)*16));
        pos = (p >> ((rf1 & 1)*16)) & 0xFFFF;
        sev[pos] = (unsigned short)n1; srf[pos] = (unsigned short)rf1;
    }
    __syncthreads();

    // pass A: restore time order inside each bucket (tiny insertion sorts)
    #pragma unroll
    for (int s = 0; s < 2; s++) {
        int i = tid + s*1024;
        int rf = srf[i];
        int pv = (i == 0) ? -1 : (int)srf[i-1];
        if (rf != pv) {
            int L = 1;
            while (i + L < NN && srf[i+L] == rf) L++;
            if (L > 1) {
                for (int a = 1; a < L; a++) {
                    unsigned short v = sev[i+a];
                    int j = a - 1;
                    while (j >= 0 && sev[i+j] > v) { sev[i+j+1] = sev[i+j]; j--; }
                    sev[i+j+1] = v;
                }
            }
        }
    }
    __syncthreads();

    // pass B: emit chain records + dump sorted event ids
    #pragma unroll
    for (int s = 0; s < 2; s++) {
        int i = tid + s*1024;
        g_sorted[b*NN + i] = sev[i];
        int rf = srf[i];
        int pv = (i == 0) ? -1 : (int)srf[i-1];
        bool isb = (rf != pv);
        int L = 0;
        if (isb) {
            L = 1;
            while (i + L < NN && srf[i+L] == rf) L++;
        }
        bool sgl = isb && (L == 1);
        unsigned bal = __ballot_sync(0xffffffffu, sgl);
        if (sgl) {
            int lane = tid & 31;
            int leader = __ffs(bal) - 1;
            int base = 0;
            if (lane == leader) base = atomicAdd(&g_ns[b], __popc(bal));
            base = __shfl_sync(bal, base, leader);
            g_single[b*NN + base + __popc(bal & ((1u << lane) - 1))] =
                (int)sev[i] | (rf << 11);
        } else if (isb) {
            int idx = atomicAdd(&g_nm[b], 1);
            g_mult[b*NN + idx] = make_int2(rf | (i << 14), L);
        }
    }
}

// K1: unified LSTM (R8 math paths, rebalanced placement).
// Blocks 0..255: one multi group each (CM=8, scalar float4 FMA, split s∈{0,1});
// then ALL 296 blocks grid-stride the singleton quads (FFMA2, Ws in shared).
__global__ void __launch_bounds__(256, 2) k_lstm(const float* __restrict__ feat,
                                                 float* __restrict__ out) {
    __shared__ float Ws[CC*GATES];                  // singles weights (32KB)
    __shared__ float bs[GATES];
    __shared__ float xsh[8][4][CC];
    __shared__ __align__(16) float ivec[CM][KTOT];  // multi path [chain][x|h]
    __shared__ int slen[CM], soff[CM];
    __shared__ int2 mds[CM];

    int tid = threadIdx.x;
    int lane = tid & 31, warp = tid >> 5;

    // stage singles weights once per block (also used for bias reads below)
    for (int i = tid; i < CC*GATES; i += 256) Ws[i] = g_WT[i];
    for (int i = tid; i < GATES; i += 256) bs[i] = g_bias[i];
    __syncthreads();

    // ================= phase 1: multi-event chains =================
    if (blockIdx.x < MUL_SLOTS) {
        int bb  = blockIdx.x & 7;
        int sub = blockIdx.x >> 3;          // 0..31
        int h = tid >> 1;                   // hidden unit 0..127
        int s = tid & 1;                    // K slice 0..1 (18 float4-groups each)
        int nm = g_nm[bb];

        float b0 = bs[h],       b1 = bs[128 + h];
        float b2 = bs[256 + h], b3 = bs[384 + h];

        for (int grp = sub*CM; grp < nm; grp += 32*CM) {
            if (tid < CM) {
                int ci = grp + tid;
                int2 m = (ci < nm) ? g_mult[bb*NN + ci] : make_int2(0, 0);
                mds[tid] = m;
                slen[tid] = m.y;
                soff[tid] = m.x >> 14;
            }
            __syncthreads();
            int rf[CM], len[CM];
            int maxlen = 0;
            #pragma unroll
            for (int c = 0; c < CM; c++) {
                int2 m = mds[c];
                rf[c] = m.x & 0x3FFF;
                len[c] = m.y;
                maxlen = max(maxlen, len[c]);
            }
            float cst[CM];
            #pragma unroll
            for (int c = 0; c < CM; c++) cst[c] = 0.f;

            for (int r = 0; r < maxlen; r++) {
                if (tid < CM*CC) {                 // stage x for the 8 chains
                    int c = tid >> 4, k = tid & 15;
                    if (slen[c] > r) {
                        int e = g_sorted[bb*NN + soff[c] + r];
                        ivec[c][k] = feat[(bb*NN + e)*CC + k];
                    }
                }
                __syncthreads();

                float a[CM][4];
                #pragma unroll
                for (int c = 0; c < CM; c++) {
                    a[c][0] = (s == 0) ? b0 : 0.f;
                    a[c][1] = (s == 0) ? b1 : 0.f;
                    a[c][2] = (s == 0) ? b2 : 0.f;
                    a[c][3] = (s == 0) ? b3 : 0.f;
                }

                if (r == 0) {
                    if (s == 0) {                  // x-only (h == 0)
                        #pragma unroll
                        for (int k4 = 0; k4 < CC/4; k4++) {
                            int base = (k4 << 2)*HID + h;
                            float4 w0 = g_W4[base];
                            float4 w1 = g_W4[base + HID];
                            float4 w2 = g_W4[base + 2*HID];
                            float4 w3 = g_W4[base + 3*HID];
                            #pragma unroll
                            for (int c = 0; c < CM; c++) {
                                float4 iv = *(const float4*)&ivec[c][k4*4];
                                a[c][0] += iv.x*w0.x + iv.y*w0.y + iv.z*w0.z + iv.w*w0.w;
                                a[c][1] += iv.x*w1.x + iv.y*w1.y + iv.z*w1.z + iv.w*w1.w;
                                a[c][2] += iv.x*w2.x + iv.y*w2.y + iv.z*w2.z + iv.w*w2.w;
                                a[c][3] += iv.x*w3.x + iv.y*w3.y + iv.z*w3.z + iv.w*w3.w;
                            }
                        }
                    }
                } else {
                    #pragma unroll 3
                    for (int j = 0; j < 18; j++) {
                        int k4 = s*18 + j;
                        int base = (k4 << 2)*HID + h;
                        float4 w0 = g_W4[base];
                        float4 w1 = g_W4[base + HID];
                        float4 w2 = g_W4[base + 2*HID];
                        float4 w3 = g_W4[base + 3*HID];
                        #pragma unroll
                        for (int c = 0; c < CM; c++) {
                            float4 iv = *(const float4*)&ivec[c][k4*4];
                            a[c][0] += iv.x*w0.x + iv.y*w0.y + iv.z*w0.z + iv.w*w0.w;
                            a[c][1] += iv.x*w1.x + iv.y*w1.y + iv.z*w1.z + iv.w*w1.w;
                            a[c][2] += iv.x*w2.x + iv.y*w2.y + iv.z*w2.z + iv.w*w2.w;
                            a[c][3] += iv.x*w3.x + iv.y*w3.y + iv.z*w3.z + iv.w*w3.w;
                        }
                    }
                }
                __syncthreads();                   // all ivec reads done

                // reduce partials across the 2 s-lanes (adjacent in warp)
                #pragma unroll
                for (int c = 0; c < CM; c++) {
                    #pragma unroll
                    for (int q = 0; q < 4; q++)
                        a[c][q] += __shfl_xor_sync(0xffffffffu, a[c][q], 1);
                }

                #pragma unroll
                for (int c = 0; c < CM; c++) {
                    if (len[c] > r) {
                        float ig = sigmoidf_(a[c][0]), fg = sigmoidf_(a[c][1]);
                        float gg = tanhf_(a[c][2]),   og = sigmoidf_(a[c][3]);
                        cst[c] = fg*cst[c] + ig*gg;
                        float hn = og * tanhf_(cst[c]);
                        if (s == 0) {
                            if (r == len[c] - 1) {
                                int y = rf[c] >> 7, x = rf[c] & 127;
                                out[((bb*HID + h)*128 + y)*128 + x] = hn;
                            } else {
                                ivec[c][CC + h] = hn;
                            }
                        }
                    }
                }
                __syncthreads();                   // h writes before next read
            }
            __syncthreads();   // done with slen/soff/ivec before next grp reload
        }
    }

    // ================= phase 2: singleton chains (all blocks) =================
    // quad slot qi: batch = qi>>9, quad index = qi&511 (4 chains per quad)
    int unit = blockIdx.x * 8 + warp;
    for (int qi = unit; qi < QUAD_SLOTS; qi += QUAD_UNITS) {
        int bb = qi >> 9;
        int idx0 = (qi & 511) << 2;
        int ns = g_ns[bb];
        if (idx0 >= ns) continue;

        int rec = -1;
        if (lane < 4 && idx0 + lane < ns) rec = g_single[bb*NN + idx0 + lane];
        __syncwarp();
        #pragma unroll
        for (int s2 = 0; s2 < 2; s2++) {
            int slot = lane + (s2 << 5);
            int c = slot >> 4, k = slot & 15;
            int rc = __shfl_sync(0xffffffffu, rec, c);
            if (rc >= 0) {
                int ev = rc & 2047;
                xsh[warp][c][k] = feat[(bb*NN + ev)*CC + k];
            }
        }
        __syncwarp();

        // acc pairs: acc2[c][2q+p] = gates q*128 + lane*4 + 2p + {0,1}
        unsigned long long acc2[4][8];
        #pragma unroll
        for (int q = 0; q < 4; q++) {
            ulonglong2 bq = *(const ulonglong2*)&bs[q*128 + (lane << 2)];
            #pragma unroll
            for (int c = 0; c < 4; c++) {
                acc2[c][2*q]   = bq.x;
                acc2[c][2*q+1] = bq.y;
            }
        }
        #pragma unroll 4
        for (int k = 0; k < CC; k++) {
            const ulonglong2* wp = (const ulonglong2*)&Ws[k*GATES + (lane << 2)];
            ulonglong2 w0 = wp[0];
            ulonglong2 w1 = wp[32];
            ulonglong2 w2 = wp[64];
            ulonglong2 w3 = wp[96];
            #pragma unroll
            for (int c = 0; c < 4; c++) {
                unsigned long long iv2 = dup2_(xsh[warp][c][k]);
                fma2_(acc2[c][0], iv2, w0.x); fma2_(acc2[c][1], iv2, w0.y);
                fma2_(acc2[c][2], iv2, w1.x); fma2_(acc2[c][3], iv2, w1.y);
                fma2_(acc2[c][4], iv2, w2.x); fma2_(acc2[c][5], iv2, w2.y);
                fma2_(acc2[c][6], iv2, w3.x); fma2_(acc2[c][7], iv2, w3.y);
            }
        }
        #pragma unroll
        for (int c = 0; c < 4; c++) {
            int rc = __shfl_sync(0xffffffffu, rec, c);
            if (rc >= 0) {
                int rf = rc >> 11;
                int y = rf >> 7, x = rf & 127;
                float2 i0 = unpack2_(acc2[c][0]), i1 = unpack2_(acc2[c][1]);
                float2 g0 = unpack2_(acc2[c][4]), g1 = unpack2_(acc2[c][5]);
                float2 o0 = unpack2_(acc2[c][6]), o1 = unpack2_(acc2[c][7]);
                float gi[4] = {i0.x, i0.y, i1.x, i1.y};
                float gg[4] = {g0.x, g0.y, g1.x, g1.y};
                float go[4] = {o0.x, o0.y, o1.x, o1.y};
                #pragma unroll
                for (int i = 0; i < 4; i++) {
                    float cn = sigmoidf_(gi[i]) * tanhf_(gg[i]);   // c_prev=0, f dead
                    float hh = sigmoidf_(go[i]) * tanhf_(cn);
                    out[((bb*HID + (lane << 2) + i)*128 + y)*128 + x] = hh;
                }
            }
        }
    }
}

extern "C" void kernel_launch(void* const* d_in, const int* in_sizes, int n_in,
                              void* d_out, int out_size) {
    const float* features = (const float*)d_in[0];
    const int*   coords   = (const int*)  d_in[1];
    const float* w_ih     = (const float*)d_in[2];
    const float* w_hh     = (const float*)d_in[3];
    const float* b_ih     = (const float*)d_in[4];
    const float* b_hh     = (const float*)d_in[5];
    float* out = (float*)d_out;

    k_prep<<<PREP_GRID, 1024>>>((float4*)out, coords, w_ih, w_hh, b_ih, b_hh);
    k_lstm<<<LSTM_GRID, 256>>>(features, out);
}